// round 5
// baseline (speedup 1.0000x reference)
#include <cuda_runtime.h>
#include <math.h>

#define Bn 2
#define Ln 2048
#define Dn 512
#define Nn 4096
#define Gn 64
#define Tn 512
#define EPSN 1e-12f
#define EPSW 1e-8f
#define NT 1024
#define NWS 32
#define CT 256
#define CE 8

// ---------------- scratch ----------------
__device__ __align__(256) float g_gn[Bn * Ln * Gn];
__device__ float g_norms[Bn * Ln];
__device__ float g_sim[Bn * Ln];
__device__ float g_coef[Bn * Ln];
__device__ int   g_lo[Bn * (Tn + 1)];

#define BARC() asm volatile("bar.sync 1, 256;" ::: "memory")

// ---------------- K1: g = x @ w^T, norms, gn ----------------
// 256 threads (8 warps), 16 tokens/block, 2 tokens/warp. grid = 256 blocks.
// w (128KB) is re-read by every block but stays L1-resident; total w L2
// traffic drops 128MB -> 32MB vs the 4tok version.
__global__ __launch_bounds__(256) void k_gn(const float* __restrict__ x,
                                            const float* __restrict__ w)
{
    int warp = threadIdx.x >> 5;
    int lane = threadIdx.x & 31;
    int tok0 = blockIdx.x * 16 + warp * 2;   // this warp's 2 tokens

    float4 xr[2][4];
#pragma unroll
    for (int t = 0; t < 2; t++) {
        const float4* xp = (const float4*)(x + (size_t)(tok0 + t) * Dn);
#pragma unroll
        for (int q = 0; q < 4; q++) xr[t][q] = xp[lane + q * 32];
    }

    __shared__ float sg[16][Gn];   // [token-in-block][group]

    for (int gi = 0; gi < Gn; gi++) {
        const float4* wp = (const float4*)(w + (size_t)gi * Dn);
        float a0 = 0.f, a1 = 0.f;
#pragma unroll
        for (int q = 0; q < 4; q++) {
            float4 wv = wp[lane + q * 32];
            a0 += xr[0][q].x * wv.x + xr[0][q].y * wv.y + xr[0][q].z * wv.z + xr[0][q].w * wv.w;
            a1 += xr[1][q].x * wv.x + xr[1][q].y * wv.y + xr[1][q].z * wv.z + xr[1][q].w * wv.w;
        }
#pragma unroll
        for (int off = 16; off > 0; off >>= 1) {
            a0 += __shfl_down_sync(0xffffffffu, a0, off);
            a1 += __shfl_down_sync(0xffffffffu, a1, off);
        }
        if (lane == 0) { sg[warp * 2][gi] = a0; sg[warp * 2 + 1][gi] = a1; }
    }
    __syncthreads();

    // norms: each warp reduces its 2 tokens (each lane sums 2 squares/token)
    __shared__ float snorm[16];
#pragma unroll
    for (int t = 0; t < 2; t++) {
        int tk = warp * 2 + t;
        float v0 = sg[tk][lane], v1 = sg[tk][lane + 32];
        float ss = v0 * v0 + v1 * v1;
#pragma unroll
        for (int off = 16; off > 0; off >>= 1) ss += __shfl_down_sync(0xffffffffu, ss, off);
        if (lane == 0) {
            float nm = sqrtf(ss);
            snorm[tk] = nm;
            g_norms[blockIdx.x * 16 + tk] = nm;
        }
    }
    __syncthreads();

    // write gn
    for (int idx = threadIdx.x; idx < 16 * Gn; idx += 256) {
        int t = idx >> 6, gi = idx & 63;
        g_gn[(size_t)(blockIdx.x * 16 + t) * Gn + gi] = sg[t][gi] / fmaxf(snorm[t], EPSN);
    }
}

// ---------------- K1b: round-1 adjacent sims ----------------
__global__ void k_sim()
{
    int b = blockIdx.y;
    int warp = threadIdx.x >> 5;
    int lane = threadIdx.x & 31;
    int i = (blockIdx.x * 8 + warp) * 2 + (lane >> 4);
    int l = lane & 15;
    float d = 0.f;
    if (i < Ln - 1) {
        const float4* A = (const float4*)(g_gn + ((size_t)b * Ln + i) * Gn);
        float4 a = A[l], c = A[l + 16];
        d = a.x * c.x + a.y * c.y + a.z * c.z + a.w * c.w;
    }
    d += __shfl_down_sync(0xffffffffu, d, 8, 16);
    d += __shfl_down_sync(0xffffffffu, d, 4, 16);
    d += __shfl_down_sync(0xffffffffu, d, 2, 16);
    d += __shfl_down_sync(0xffffffffu, d, 1, 16);
    if (l == 0 && i < Ln - 1) g_sim[b * Ln + i] = d;
}

// ---------------- K2: merge plan (1 block per batch) ----------------
// flags bit0: matched, bit1: selected, bit2: dirty
__global__ __launch_bounds__(NT) void k_merge()
{
    const int b = blockIdx.x;
    const int tid = threadIdx.x;
    const int wid = tid >> 5;
    const int lane = tid & 31;
    const int half = lane >> 4;
    const int l = lane & 15;

    __shared__ float s_norm[Ln];
    __shared__ float s_sim[Ln];
    __shared__ unsigned short s_lo[Ln + 1];
    __shared__ unsigned char s_flag[Ln];
    __shared__ unsigned long long s_key[Ln];
    __shared__ int s_part[NWS];
    __shared__ int sh_n, sh_rem, sh_cnt;

    float* gnb   = g_gn + (size_t)b * Ln * Gn;
    float* coefb = g_coef + b * Ln;

    for (int i = tid; i < Ln; i += NT) {
        s_norm[i] = g_norms[b * Ln + i];
        s_sim[i]  = g_sim[b * Ln + i];
        s_lo[i]   = (unsigned short)i;
        s_flag[i] = 0;
        coefb[i]  = 1.0f;
    }
    if (tid == 0) { s_lo[Ln] = (unsigned short)Ln; sh_n = Ln; sh_rem = Ln - Tn; }
    __syncthreads();

    for (int round = 0; round < 24; round++) {
        int n = sh_n, rem = sh_rem;
        if (rem <= 0 || n < 2) break;
        int r_step = min(rem, n >> 1);

        // A) recompute dirty sims (all warps, half-warp cooperative)
        for (int bse = wid * 2; bse < n - 1; bse += NWS * 2) {
            int i = bse + half;
            bool valid = (i < n - 1) && (s_flag[i] & 4);
            float d = 0.f;
            if (valid) {
                const float4* Ap = (const float4*)(gnb + (size_t)s_lo[i] * Gn);
                const float4* Bp = (const float4*)(gnb + (size_t)s_lo[i + 1] * Gn);
                float4 a = Ap[l], c = Bp[l];
                d = a.x * c.x + a.y * c.y + a.z * c.z + a.w * c.w;
            }
            d += __shfl_down_sync(0xffffffffu, d, 8, 16);
            d += __shfl_down_sync(0xffffffffu, d, 4, 16);
            d += __shfl_down_sync(0xffffffffu, d, 2, 16);
            d += __shfl_down_sync(0xffffffffu, d, 1, 16);
            if (valid && l == 0) { s_sim[i] = d; s_flag[i] = (unsigned char)(s_flag[i] & ~4); }
        }
        __syncthreads();

        // B) closed-form greedy matching + count + selection (control threads)
        if (tid < CT) {
            int base = tid * CE;
            unsigned pre = 0, parF = 0, parB = 0;

            int run = -1;
#pragma unroll
            for (int e = 0; e < CE; e++) {
                int i = base + e;
                if (i < n - 1) {
                    bool bnd = (i == 0) || (s_sim[i - 1] < s_sim[i]);
                    if (bnd) run = i;
                    if (run < 0) pre |= (1u << e);
                    else if (((i - run) & 1) == 0) parF |= (1u << e);
                }
            }
            int incl = run;
#pragma unroll
            for (int off = 1; off < 32; off <<= 1) {
                int v = __shfl_up_sync(0xffffffffu, incl, off);
                if (lane >= off) incl = max(incl, v);
            }
            int excl = __shfl_up_sync(0xffffffffu, incl, 1);
            if (lane == 0) excl = -1;
            if (lane == 31) s_part[wid] = incl;
            BARC();
            {
                int carry = excl;
                for (int w2 = 0; w2 < wid; w2++) carry = max(carry, s_part[w2]);
                if (pre) {
#pragma unroll
                    for (int e = 0; e < CE; e++)
                        if ((pre >> e) & 1u) {
                            if ((((base + e) - carry) & 1) == 0) parF |= (1u << e);
                        }
                }
            }
            BARC();

            pre = 0; run = 0x7fffffff;
#pragma unroll
            for (int e = CE - 1; e >= 0; e--) {
                int i = base + e;
                if (i < n - 1) {
                    bool bnd = (i == n - 2) || (s_sim[i + 1] <= s_sim[i]);
                    if (bnd) run = i;
                    if (run == 0x7fffffff) pre |= (1u << e);
                    else if (((run - i) & 1) == 0) parB |= (1u << e);
                }
            }
            int sincl = run;
#pragma unroll
            for (int off = 1; off < 32; off <<= 1) {
                int v = __shfl_down_sync(0xffffffffu, sincl, off);
                if (lane + off < 32) sincl = min(sincl, v);
            }
            int sexcl = __shfl_down_sync(0xffffffffu, sincl, 1);
            if (lane == 31) sexcl = 0x7fffffff;
            if (lane == 0) s_part[wid] = sincl;
            BARC();
            {
                int carry = sexcl;
                for (int w2 = wid + 1; w2 < CT / 32; w2++) carry = min(carry, s_part[w2]);
                if (pre) {
#pragma unroll
                    for (int e = 0; e < CE; e++)
                        if ((pre >> e) & 1u) {
                            if (((carry - (base + e)) & 1) == 0) parB |= (1u << e);
                        }
                }
            }

            unsigned tk = parF & parB;
            int lm = 0;
#pragma unroll
            for (int e = 0; e < CE; e++) {
                int i = base + e;
                if (i < n - 1) {
                    unsigned t1 = (tk >> e) & 1u;
                    s_flag[i] = (unsigned char)((s_flag[i] & 4) | t1);
                    lm += (int)t1;
                }
            }
#pragma unroll
            for (int off = 16; off > 0; off >>= 1) lm += __shfl_down_sync(0xffffffffu, lm, off);
            BARC();
            if (lane == 0) s_part[wid] = lm;
            BARC();
            int m = 0;
            for (int w2 = 0; w2 < CT / 32; w2++) m += s_part[w2];
            int cnt = min(m, r_step);

            if (m > r_step) {
                int P = 1; while (P < n - 1) P <<= 1;
                for (int i = tid; i < P; i += CT) {
                    unsigned long long key = 0ull;
                    if (i < n - 1 && (s_flag[i] & 1)) {
                        unsigned u = __float_as_uint(s_sim[i]);
                        unsigned sk = (u & 0x80000000u) ? ~u : (u | 0x80000000u);
                        key = ((unsigned long long)sk << 16) | (unsigned)(Ln - 1 - i);
                    }
                    s_key[i] = key;
                }
                BARC();
                for (int kk = 2; kk <= P; kk <<= 1) {
                    for (int j = kk >> 1; j > 0; j >>= 1) {
                        for (int i = tid; i < P; i += CT) {
                            int ixj = i ^ j;
                            if (ixj > i) {
                                unsigned long long a = s_key[i], c = s_key[ixj];
                                bool dir = ((i & kk) == 0);
                                if (dir ? (a < c) : (a > c)) { s_key[i] = c; s_key[ixj] = a; }
                            }
                        }
                        BARC();
                    }
                }
                for (int r = tid; r < r_step; r += CT) {
                    int idx = Ln - 1 - (int)(s_key[r] & 0xFFFFull);
                    s_flag[idx] |= 2;
                }
            } else {
                for (int i = tid; i < n - 1; i += CT)
                    if (s_flag[i] & 1) s_flag[i] |= 2;
            }
            if (tid == 0) sh_cnt = cnt;
        }
        __syncthreads();
        int cnt = sh_cnt;

        // E) apply merges (all warps, half-warp cooperative)
        for (int bse = wid * 2; bse < n - 1; bse += NWS * 2) {
            int i = bse + half;
            bool valid = (i < n - 1) && (s_flag[i] & 2);
            float wi = 0.f, wj = 0.f, tot = 1.f;
            int ta = 0, tb = 0, tc = 0;
            float4 a = make_float4(0.f, 0.f, 0.f, 0.f);
            float4 c = a;
            float4* Ap = 0;
            if (valid) {
                wi = s_norm[i]; wj = s_norm[i + 1];
                tot = wi + wj + EPSW;
                ta = s_lo[i]; tb = s_lo[i + 1]; tc = s_lo[i + 2];
                Ap = (float4*)(gnb + (size_t)ta * Gn);
                const float4* Bp = (const float4*)(gnb + (size_t)tb * Gn);
                a = Ap[l]; c = Bp[l];
            }
            float mx = (wi * a.x + wj * c.x) / tot;
            float my = (wi * a.y + wj * c.y) / tot;
            float mz = (wi * a.z + wj * c.z) / tot;
            float mw = (wi * a.w + wj * c.w) / tot;
            float ssq = mx * mx + my * my + mz * mz + mw * mw;
            ssq += __shfl_xor_sync(0xffffffffu, ssq, 8, 16);
            ssq += __shfl_xor_sync(0xffffffffu, ssq, 4, 16);
            ssq += __shfl_xor_sync(0xffffffffu, ssq, 2, 16);
            ssq += __shfl_xor_sync(0xffffffffu, ssq, 1, 16);
            if (valid) {
                float inv = 1.f / fmaxf(sqrtf(ssq), EPSN);
                float4 o; o.x = mx * inv; o.y = my * inv; o.z = mz * inv; o.w = mw * inv;
                Ap[l] = o;
                float fa = wi / tot, fb = wj / tot;
                for (int t = ta + l; t < tb; t += 16) coefb[t] *= fa;
                for (int t = tb + l; t < tc; t += 16) coefb[t] *= fb;
                if (l == 0) {
                    s_norm[i] = (wi + wj) * 0.5f;
                    s_flag[i] |= 4;
                    if (i > 0) s_flag[i - 1] |= 4;
                }
            }
        }
        __syncthreads();

        // F) compaction (all threads, 2 elems each, warp scan + partials)
        {
            int b0 = tid * 2, b1 = tid * 2 + 1;
            int k0 = 0, k1 = 0;
            float n0 = 0.f, n1 = 0.f, si0 = 0.f, si1 = 0.f;
            unsigned short lo0 = 0, lo1 = 0;
            unsigned char f0 = 0, f1 = 0;
            if (b0 < n) {
                k0 = !(b0 > 0 && (s_flag[b0 - 1] & 2));
                if (k0) { n0 = s_norm[b0]; si0 = s_sim[b0]; lo0 = s_lo[b0]; f0 = s_flag[b0]; }
            }
            if (b1 < n) {
                k1 = !((s_flag[b1 - 1] & 2) != 0);
                if (k1) { n1 = s_norm[b1]; si1 = s_sim[b1]; lo1 = s_lo[b1]; f1 = s_flag[b1]; }
            }
            int loc = k0 + k1;
            int inc = loc;
#pragma unroll
            for (int off = 1; off < 32; off <<= 1) {
                int v = __shfl_up_sync(0xffffffffu, inc, off);
                if (lane >= off) inc += v;
            }
            int exc = inc - loc;
            if (lane == 31) s_part[wid] = inc;
            __syncthreads();
            int carry = 0;
            for (int w2 = 0; w2 < wid; w2++) carry += s_part[w2];
            int p0 = carry + exc;
            int p1 = p0 + k0;
            __syncthreads();
            if (k0) { s_norm[p0] = n0; s_sim[p0] = si0; s_lo[p0] = lo0; s_flag[p0] = f0; }
            if (k1) { s_norm[p1] = n1; s_sim[p1] = si1; s_lo[p1] = lo1; s_flag[p1] = f1; }
            if (tid == 0) {
                sh_n = n - cnt;
                sh_rem = rem - cnt;
            }
            __syncthreads();
            if (tid == 0) s_lo[n - cnt] = (unsigned short)Ln;
            __syncthreads();
        }
    }

    for (int k = tid; k <= Tn; k += NT) g_lo[b * (Tn + 1) + k] = (int)s_lo[k];
}

// ---------------- K3: apply plan (bandwidth-bound) ----------------
__global__ void k_apply(const float* __restrict__ x, const float* __restrict__ s,
                        float* __restrict__ out)
{
    int kslot = blockIdx.x;
    int chunk = blockIdx.y;
    int b = blockIdx.z;
    int lo = g_lo[b * (Tn + 1) + kslot];
    int hi = g_lo[b * (Tn + 1) + kslot + 1];
    int t4 = threadIdx.x;

    if (chunk == 0) {
        float4 acc = make_float4(0.f, 0.f, 0.f, 0.f);
#pragma unroll 4
        for (int t = lo; t < hi; t++) {
            float c = g_coef[b * Ln + t];
            float4 v = ((const float4*)(x + ((size_t)b * Ln + t) * Dn))[t4];
            acc.x += c * v.x; acc.y += c * v.y; acc.z += c * v.z; acc.w += c * v.w;
        }
        ((float4*)(out + ((size_t)b * Tn + kslot) * Dn))[t4] = acc;
    } else {
        int c0 = (chunk - 1) * 512;
        float4 acc = make_float4(0.f, 0.f, 0.f, 0.f);
#pragma unroll 4
        for (int t = lo; t < hi; t++) {
            float4 v = ((const float4*)(s + ((size_t)b * Ln + t) * Nn + c0))[t4];
            acc.x += v.x; acc.y += v.y; acc.z += v.z; acc.w += v.w;
        }
        ((float4*)(out + (size_t)Bn * Tn * Dn + ((size_t)b * Tn + kslot) * Nn + c0))[t4] = acc;
    }
}

// ---------------- launch ----------------
extern "C" void kernel_launch(void* const* d_in, const int* in_sizes, int n_in,
                              void* d_out, int out_size)
{
    const float* x = (const float*)d_in[0];
    const float* src = (const float*)d_in[1];
    const float* w = (const float*)d_in[2];
    float* out = (float*)d_out;

    k_gn<<<Bn * Ln / 16, 256>>>(x, w);
    k_sim<<<dim3(128, Bn), 256>>>();
    k_merge<<<Bn, NT>>>();
    dim3 g3(Tn, 1 + Nn / 512, Bn);
    k_apply<<<g3, 128>>>(x, src, out);
}

// round 6
// speedup vs baseline: 1.1034x; 1.1034x over previous
#include <cuda_runtime.h>
#include <math.h>

#define Bn 2
#define Ln 2048
#define Dn 512
#define Nn 4096
#define Gn 64
#define Tn 512
#define EPSN 1e-12f
#define EPSW 1e-8f
#define NT 1024
#define NWS 32
#define CT 256
#define CE 8

// ---------------- scratch ----------------
__device__ __align__(256) float g_gn[Bn * Ln * Gn];
__device__ float g_norms[Bn * Ln];
__device__ float g_sim[Bn * Ln];
__device__ float g_coef[Bn * Ln];
__device__ int   g_lo[Bn * (Tn + 1)];

#define BARC() asm volatile("bar.sync 1, 256;" ::: "memory")

// ---------------- K1: g = x @ w^T, norms, gn (R1 exact: measured 27.6us) ------
__global__ void k_gn(const float* __restrict__ x, const float* __restrict__ w)
{
    int tok0 = blockIdx.x * 4;
    int warp = threadIdx.x >> 5;
    int lane = threadIdx.x & 31;

    float4 xr[4][4];
#pragma unroll
    for (int t = 0; t < 4; t++) {
        const float4* xp = (const float4*)(x + (size_t)(tok0 + t) * Dn);
#pragma unroll
        for (int q = 0; q < 4; q++) xr[t][q] = xp[lane + q * 32];
    }

    __shared__ float sg[4][Gn];
    __shared__ float snorm[4];

    for (int gg = 0; gg < 32; gg++) {
        int gi = warp * 32 + gg;
        const float4* wp = (const float4*)(w + (size_t)gi * Dn);
        float a0 = 0.f, a1 = 0.f, a2 = 0.f, a3 = 0.f;
#pragma unroll
        for (int q = 0; q < 4; q++) {
            float4 wv = wp[lane + q * 32];
            a0 += xr[0][q].x * wv.x + xr[0][q].y * wv.y + xr[0][q].z * wv.z + xr[0][q].w * wv.w;
            a1 += xr[1][q].x * wv.x + xr[1][q].y * wv.y + xr[1][q].z * wv.z + xr[1][q].w * wv.w;
            a2 += xr[2][q].x * wv.x + xr[2][q].y * wv.y + xr[2][q].z * wv.z + xr[2][q].w * wv.w;
            a3 += xr[3][q].x * wv.x + xr[3][q].y * wv.y + xr[3][q].z * wv.z + xr[3][q].w * wv.w;
        }
#pragma unroll
        for (int off = 16; off > 0; off >>= 1) {
            a0 += __shfl_down_sync(0xffffffffu, a0, off);
            a1 += __shfl_down_sync(0xffffffffu, a1, off);
            a2 += __shfl_down_sync(0xffffffffu, a2, off);
            a3 += __shfl_down_sync(0xffffffffu, a3, off);
        }
        if (lane == 0) { sg[0][gi] = a0; sg[1][gi] = a1; sg[2][gi] = a2; sg[3][gi] = a3; }
    }
    __syncthreads();

    if (threadIdx.x < 4) {
        int t = threadIdx.x;
        float ssum = 0.f;
        for (int gi = 0; gi < Gn; gi++) { float v = sg[t][gi]; ssum += v * v; }
        float nm = sqrtf(ssum);
        snorm[t] = nm;
        g_norms[tok0 + t] = nm;
    }
    __syncthreads();

    for (int idx = threadIdx.x; idx < 4 * Gn; idx += 64) {
        int t = idx >> 6, gi = idx & 63;
        g_gn[(size_t)(tok0 + t) * Gn + gi] = sg[t][gi] / fmaxf(snorm[t], EPSN);
    }
}

// ---------------- K1b: round-1 adjacent sims ----------------
__global__ void k_sim()
{
    int b = blockIdx.y;
    int warp = threadIdx.x >> 5;
    int lane = threadIdx.x & 31;
    int i = (blockIdx.x * 8 + warp) * 2 + (lane >> 4);
    int l = lane & 15;
    float d = 0.f;
    if (i < Ln - 1) {
        const float4* A = (const float4*)(g_gn + ((size_t)b * Ln + i) * Gn);
        float4 a = A[l], c = A[l + 16];
        d = a.x * c.x + a.y * c.y + a.z * c.z + a.w * c.w;
    }
    d += __shfl_down_sync(0xffffffffu, d, 8, 16);
    d += __shfl_down_sync(0xffffffffu, d, 4, 16);
    d += __shfl_down_sync(0xffffffffu, d, 2, 16);
    d += __shfl_down_sync(0xffffffffu, d, 1, 16);
    if (l == 0 && i < Ln - 1) g_sim[b * Ln + i] = d;
}

// ---------------- K2: merge plan (1 block per batch, closed-form matching) ----
// flags bit0: matched, bit1: selected, bit2: dirty
__global__ __launch_bounds__(NT) void k_merge()
{
    const int b = blockIdx.x;
    const int tid = threadIdx.x;
    const int wid = tid >> 5;
    const int lane = tid & 31;
    const int half = lane >> 4;
    const int l = lane & 15;

    __shared__ float s_norm[Ln];
    __shared__ float s_sim[Ln];
    __shared__ float s_coef[Ln];
    __shared__ unsigned short s_lo[Ln + 1];
    __shared__ unsigned char s_flag[Ln];
    __shared__ unsigned long long s_key[Ln];
    __shared__ int s_part[NWS];
    __shared__ int sh_n, sh_rem, sh_cnt;

    float* gnb   = g_gn + (size_t)b * Ln * Gn;
    float* coefb = g_coef + b * Ln;

    for (int i = tid; i < Ln; i += NT) {
        s_norm[i] = g_norms[b * Ln + i];
        s_sim[i]  = g_sim[b * Ln + i];
        s_lo[i]   = (unsigned short)i;
        s_flag[i] = 0;
        s_coef[i] = 1.0f;
    }
    if (tid == 0) { s_lo[Ln] = (unsigned short)Ln; sh_n = Ln; sh_rem = Ln - Tn; }
    __syncthreads();

    for (int round = 0; round < 24; round++) {
        int n = sh_n, rem = sh_rem;
        if (rem <= 0 || n < 2) break;
        int r_step = min(rem, n >> 1);

        // A) recompute dirty sims (all warps, half-warp cooperative)
        for (int bse = wid * 2; bse < n - 1; bse += NWS * 2) {
            int i = bse + half;
            bool valid = (i < n - 1) && (s_flag[i] & 4);
            float d = 0.f;
            if (valid) {
                const float4* Ap = (const float4*)(gnb + (size_t)s_lo[i] * Gn);
                const float4* Bp = (const float4*)(gnb + (size_t)s_lo[i + 1] * Gn);
                float4 a = Ap[l], c = Bp[l];
                d = a.x * c.x + a.y * c.y + a.z * c.z + a.w * c.w;
            }
            d += __shfl_down_sync(0xffffffffu, d, 8, 16);
            d += __shfl_down_sync(0xffffffffu, d, 4, 16);
            d += __shfl_down_sync(0xffffffffu, d, 2, 16);
            d += __shfl_down_sync(0xffffffffu, d, 1, 16);
            if (valid && l == 0) { s_sim[i] = d; s_flag[i] = (unsigned char)(s_flag[i] & ~4); }
        }
        __syncthreads();

        // B) closed-form greedy matching + count + selection (control threads)
        if (tid < CT) {
            int base = tid * CE;
            unsigned pre = 0, parF = 0, parB = 0;

            int run = -1;
#pragma unroll
            for (int e = 0; e < CE; e++) {
                int i = base + e;
                if (i < n - 1) {
                    bool bnd = (i == 0) || (s_sim[i - 1] < s_sim[i]);
                    if (bnd) run = i;
                    if (run < 0) pre |= (1u << e);
                    else if (((i - run) & 1) == 0) parF |= (1u << e);
                }
            }
            int incl = run;
#pragma unroll
            for (int off = 1; off < 32; off <<= 1) {
                int v = __shfl_up_sync(0xffffffffu, incl, off);
                if (lane >= off) incl = max(incl, v);
            }
            int excl = __shfl_up_sync(0xffffffffu, incl, 1);
            if (lane == 0) excl = -1;
            if (lane == 31) s_part[wid] = incl;
            BARC();
            {
                int carry = excl;
                for (int w2 = 0; w2 < wid; w2++) carry = max(carry, s_part[w2]);
                if (pre) {
#pragma unroll
                    for (int e = 0; e < CE; e++)
                        if ((pre >> e) & 1u) {
                            if ((((base + e) - carry) & 1) == 0) parF |= (1u << e);
                        }
                }
            }
            BARC();

            pre = 0; run = 0x7fffffff;
#pragma unroll
            for (int e = CE - 1; e >= 0; e--) {
                int i = base + e;
                if (i < n - 1) {
                    bool bnd = (i == n - 2) || (s_sim[i + 1] <= s_sim[i]);
                    if (bnd) run = i;
                    if (run == 0x7fffffff) pre |= (1u << e);
                    else if (((run - i) & 1) == 0) parB |= (1u << e);
                }
            }
            int sincl = run;
#pragma unroll
            for (int off = 1; off < 32; off <<= 1) {
                int v = __shfl_down_sync(0xffffffffu, sincl, off);
                if (lane + off < 32) sincl = min(sincl, v);
            }
            int sexcl = __shfl_down_sync(0xffffffffu, sincl, 1);
            if (lane == 31) sexcl = 0x7fffffff;
            if (lane == 0) s_part[wid] = sincl;
            BARC();
            {
                int carry = sexcl;
                for (int w2 = wid + 1; w2 < CT / 32; w2++) carry = min(carry, s_part[w2]);
                if (pre) {
#pragma unroll
                    for (int e = 0; e < CE; e++)
                        if ((pre >> e) & 1u) {
                            if (((carry - (base + e)) & 1) == 0) parB |= (1u << e);
                        }
                }
            }

            unsigned tk = parF & parB;
            int lm = 0;
#pragma unroll
            for (int e = 0; e < CE; e++) {
                int i = base + e;
                if (i < n - 1) {
                    unsigned t1 = (tk >> e) & 1u;
                    s_flag[i] = (unsigned char)((s_flag[i] & 4) | t1);
                    lm += (int)t1;
                }
            }
#pragma unroll
            for (int off = 16; off > 0; off >>= 1) lm += __shfl_down_sync(0xffffffffu, lm, off);
            BARC();
            if (lane == 0) s_part[wid] = lm;
            BARC();
            int m = 0;
            for (int w2 = 0; w2 < CT / 32; w2++) m += s_part[w2];
            int cnt = min(m, r_step);

            if (m > r_step) {
                int P = 1; while (P < n - 1) P <<= 1;
                for (int i = tid; i < P; i += CT) {
                    unsigned long long key = 0ull;
                    if (i < n - 1 && (s_flag[i] & 1)) {
                        unsigned u = __float_as_uint(s_sim[i]);
                        unsigned sk = (u & 0x80000000u) ? ~u : (u | 0x80000000u);
                        key = ((unsigned long long)sk << 16) | (unsigned)(Ln - 1 - i);
                    }
                    s_key[i] = key;
                }
                BARC();
                for (int kk = 2; kk <= P; kk <<= 1) {
                    for (int j = kk >> 1; j > 0; j >>= 1) {
                        for (int i = tid; i < P; i += CT) {
                            int ixj = i ^ j;
                            if (ixj > i) {
                                unsigned long long a = s_key[i], c = s_key[ixj];
                                bool dir = ((i & kk) == 0);
                                if (dir ? (a < c) : (a > c)) { s_key[i] = c; s_key[ixj] = a; }
                            }
                        }
                        BARC();
                    }
                }
                for (int r = tid; r < r_step; r += CT) {
                    int idx = Ln - 1 - (int)(s_key[r] & 0xFFFFull);
                    s_flag[idx] |= 2;
                }
            } else {
                for (int i = tid; i < n - 1; i += CT)
                    if (s_flag[i] & 1) s_flag[i] |= 2;
            }
            if (tid == 0) sh_cnt = cnt;
        }
        __syncthreads();
        int cnt = sh_cnt;

        // E) apply merges (all warps, half-warp cooperative; coef in shared)
        for (int bse = wid * 2; bse < n - 1; bse += NWS * 2) {
            int i = bse + half;
            bool valid = (i < n - 1) && (s_flag[i] & 2);
            float wi = 0.f, wj = 0.f, tot = 1.f;
            int ta = 0, tb = 0, tc = 0;
            float4 a = make_float4(0.f, 0.f, 0.f, 0.f);
            float4 c = a;
            float4* Ap = 0;
            if (valid) {
                wi = s_norm[i]; wj = s_norm[i + 1];
                tot = wi + wj + EPSW;
                ta = s_lo[i]; tb = s_lo[i + 1]; tc = s_lo[i + 2];
                Ap = (float4*)(gnb + (size_t)ta * Gn);
                const float4* Bp = (const float4*)(gnb + (size_t)tb * Gn);
                a = Ap[l]; c = Bp[l];
            }
            float mx = (wi * a.x + wj * c.x) / tot;
            float my = (wi * a.y + wj * c.y) / tot;
            float mz = (wi * a.z + wj * c.z) / tot;
            float mw = (wi * a.w + wj * c.w) / tot;
            float ssq = mx * mx + my * my + mz * mz + mw * mw;
            ssq += __shfl_xor_sync(0xffffffffu, ssq, 8, 16);
            ssq += __shfl_xor_sync(0xffffffffu, ssq, 4, 16);
            ssq += __shfl_xor_sync(0xffffffffu, ssq, 2, 16);
            ssq += __shfl_xor_sync(0xffffffffu, ssq, 1, 16);
            if (valid) {
                float inv = 1.f / fmaxf(sqrtf(ssq), EPSN);
                float4 o; o.x = mx * inv; o.y = my * inv; o.z = mz * inv; o.w = mw * inv;
                Ap[l] = o;
                float fa = wi / tot, fb = wj / tot;
                for (int t = ta + l; t < tb; t += 16) s_coef[t] *= fa;
                for (int t = tb + l; t < tc; t += 16) s_coef[t] *= fb;
                if (l == 0) {
                    s_norm[i] = (wi + wj) * 0.5f;
                    s_flag[i] |= 4;
                    if (i > 0) s_flag[i - 1] |= 4;
                }
            }
        }
        __syncthreads();

        // F) compaction (all threads, 2 elems each, warp scan + partials)
        {
            int b0 = tid * 2, b1 = tid * 2 + 1;
            int k0 = 0, k1 = 0;
            float n0 = 0.f, n1 = 0.f, si0 = 0.f, si1 = 0.f;
            unsigned short lo0 = 0, lo1 = 0;
            unsigned char f0 = 0, f1 = 0;
            if (b0 < n) {
                k0 = !(b0 > 0 && (s_flag[b0 - 1] & 2));
                if (k0) { n0 = s_norm[b0]; si0 = s_sim[b0]; lo0 = s_lo[b0]; f0 = s_flag[b0]; }
            }
            if (b1 < n) {
                k1 = !((s_flag[b1 - 1] & 2) != 0);
                if (k1) { n1 = s_norm[b1]; si1 = s_sim[b1]; lo1 = s_lo[b1]; f1 = s_flag[b1]; }
            }
            int loc = k0 + k1;
            int inc = loc;
#pragma unroll
            for (int off = 1; off < 32; off <<= 1) {
                int v = __shfl_up_sync(0xffffffffu, inc, off);
                if (lane >= off) inc += v;
            }
            int exc = inc - loc;
            if (lane == 31) s_part[wid] = inc;
            __syncthreads();
            int carry = 0;
            for (int w2 = 0; w2 < wid; w2++) carry += s_part[w2];
            int p0 = carry + exc;
            int p1 = p0 + k0;
            __syncthreads();
            if (k0) { s_norm[p0] = n0; s_sim[p0] = si0; s_lo[p0] = lo0; s_flag[p0] = f0; }
            if (k1) { s_norm[p1] = n1; s_sim[p1] = si1; s_lo[p1] = lo1; s_flag[p1] = f1; }
            if (tid == 0) { sh_n = n - cnt; sh_rem = rem - cnt; }
            __syncthreads();
            if (tid == 0) s_lo[n - cnt] = (unsigned short)Ln;
            __syncthreads();
        }
    }

    for (int i = tid; i < Ln; i += NT) coefb[i] = s_coef[i];
    for (int k = tid; k <= Tn; k += NT) g_lo[b * (Tn + 1) + k] = (int)s_lo[k];
}

// ---------------- K3: apply plan (R2 exact: measured 16.4us) ----------------
__global__ void k_apply(const float* __restrict__ x, const float* __restrict__ s,
                        float* __restrict__ out)
{
    int kslot = blockIdx.x;
    int chunk = blockIdx.y;
    int b = blockIdx.z;
    int lo = g_lo[b * (Tn + 1) + kslot];
    int hi = g_lo[b * (Tn + 1) + kslot + 1];
    int t4 = threadIdx.x;

    if (chunk == 0) {
        float4 acc = make_float4(0.f, 0.f, 0.f, 0.f);
#pragma unroll 2
        for (int t = lo; t < hi; t++) {
            float c = g_coef[b * Ln + t];
            float4 v = ((const float4*)(x + ((size_t)b * Ln + t) * Dn))[t4];
            acc.x += c * v.x; acc.y += c * v.y; acc.z += c * v.z; acc.w += c * v.w;
        }
        ((float4*)(out + ((size_t)b * Tn + kslot) * Dn))[t4] = acc;
    } else {
        int c0 = (chunk - 1) * 512;
        float4 acc = make_float4(0.f, 0.f, 0.f, 0.f);
#pragma unroll 2
        for (int t = lo; t < hi; t++) {
            float4 v = ((const float4*)(s + ((size_t)b * Ln + t) * Nn + c0))[t4];
            acc.x += v.x; acc.y += v.y; acc.z += v.z; acc.w += v.w;
        }
        ((float4*)(out + (size_t)Bn * Tn * Dn + ((size_t)b * Tn + kslot) * Nn + c0))[t4] = acc;
    }
}

// ---------------- launch ----------------
extern "C" void kernel_launch(void* const* d_in, const int* in_sizes, int n_in,
                              void* d_out, int out_size)
{
    const float* x = (const float*)d_in[0];
    const float* src = (const float*)d_in[1];
    const float* w = (const float*)d_in[2];
    float* out = (float*)d_out;

    k_gn<<<Bn * Ln / 4, 64>>>(x, w);
    k_sim<<<dim3(128, Bn), 256>>>();
    k_merge<<<Bn, NT>>>();
    dim3 g3(Tn, 1 + Nn / 512, Bn);
    k_apply<<<g3, 128>>>(x, src, out);
}